// round 6
// baseline (speedup 1.0000x reference)
#include <cuda_runtime.h>
#include <cuda_fp16.h>
#include <cstdint>

// ============================================================================
// BSpline via warp-level mma.sync (HMMA).
//   out[b,o] = sum_{i,c} basis(x[b,i])[c] * cp[i,c,o]
//   = GEMM: A (rows x 768) * B (768 x 64), k = i*12 + c.
// R6: warp tile M32xN32 (4 warps/CTA, 2 CTAs/SM) -> B L1 traffic halved;
//   B repacked so each lane loads 32B contiguous (2 x LDG.128 per kstep);
//   phase-1 stores paired into st.shared.v2.u64.
// ============================================================================

#define DIMS 64
#define KSTEPS 48          // 768 / 16
#define M_TILE 64
#define THREADS 128

#define A_PITCH_B 1552     // bytes per A row: 776 halfs; odd multiple of 16B
#define SMEM_A_BYTES (M_TILE * A_PITCH_B)        // 99328
#define SMEM_TAB SMEM_A_BYTES                    // 9 * 12 floats
#define SMEM_TOTAL (SMEM_A_BYTES + 512)

// B fragments, lane-contiguous: g_Bf2[((ks*2+nb)*32+lid)*2+q] (uint4)
//   uint4 = { frag(n0).kq01, frag(n0).kq89, frag(n0+8).kq01, frag(n0+8).kq89 }
//   n0 = nb*32 + (lid>>2) + q*16, kq = lid&3, k0 = ks*16+kq*2.
__device__ uint4 g_Bf2[KSTEPS * 2 * 32 * 2];

static __device__ __forceinline__ uint32_t s2u(const void* p) {
    uint32_t a;
    asm("{ .reg .u64 t; cvta.to.shared.u64 t, %1; cvt.u32.u64 %0, t; }" : "=r"(a) : "l"(p));
    return a;
}

static __device__ __forceinline__ void ldsm_x4(uint32_t& r0, uint32_t& r1,
                                               uint32_t& r2, uint32_t& r3,
                                               uint32_t addr) {
    asm volatile("ldmatrix.sync.aligned.m8n8.x4.shared.b16 {%0,%1,%2,%3}, [%4];"
                 : "=r"(r0), "=r"(r1), "=r"(r2), "=r"(r3) : "r"(addr));
}

static __device__ __forceinline__ void mma16816(float& d0, float& d1, float& d2, float& d3,
                                                uint32_t a0, uint32_t a1, uint32_t a2, uint32_t a3,
                                                uint32_t b0, uint32_t b1) {
    asm("mma.sync.aligned.m16n8k16.row.col.f32.f16.f16.f32 "
        "{%0,%1,%2,%3}, {%4,%5,%6,%7}, {%8,%9}, {%0,%1,%2,%3};"
        : "+f"(d0), "+f"(d1), "+f"(d2), "+f"(d3)
        : "r"(a0), "r"(a1), "r"(a2), "r"(a3), "r"(b0), "r"(b1));
}

static __device__ __forceinline__ float knotv(int k) {
    int v = max(0, min(9, k - 3));
    return (float)v / 9.0f;
}

static __device__ __forceinline__ uint32_t packh2(float a, float b) {
    uint32_t r;
    asm("cvt.rn.f16x2.f32 %0, %2, %1;" : "=r"(r) : "f"(a), "f"(b));
    return r;
}

// ---------------------------------------------------------------------------
// Prep: cp fp32 (seen as [k][o], k = i*12+c) -> lane-contiguous fp16 frags.
// ---------------------------------------------------------------------------
__global__ void bspline_prep_kernel(const float* __restrict__ cp) {
    int tid = blockIdx.x * blockDim.x + threadIdx.x;
    if (tid < KSTEPS * 2 * 32 * 2) {
        int q = tid & 1;
        int lid = (tid >> 1) & 31;
        int nb = (tid >> 6) & 1;
        int ks = tid >> 7;
        int n0 = nb * 32 + (lid >> 2) + q * 16;
        int k0 = ks * 16 + (lid & 3) * 2;
        uint4 v;
        v.x = packh2(cp[(k0 + 0) * 64 + n0],     cp[(k0 + 1) * 64 + n0]);
        v.y = packh2(cp[(k0 + 8) * 64 + n0],     cp[(k0 + 9) * 64 + n0]);
        v.z = packh2(cp[(k0 + 0) * 64 + n0 + 8], cp[(k0 + 1) * 64 + n0 + 8]);
        v.w = packh2(cp[(k0 + 8) * 64 + n0 + 8], cp[(k0 + 9) * 64 + n0 + 8]);
        g_Bf2[tid] = v;
    }
}

// ---------------------------------------------------------------------------
// Main kernel: one CTA = 64 rows, 4 warps = 2(M) x 2(N), warp tile M32xN32.
// ---------------------------------------------------------------------------
__global__ __launch_bounds__(THREADS, 2)
void bspline_hmma_kernel(const float* __restrict__ x,
                         float* __restrict__ out,
                         int nrows)
{
    extern __shared__ char sm[];
    const uint32_t sb = s2u(sm);
    const int t = threadIdx.x;
    const int wid = t >> 5;
    const int lid = t & 31;
    const int row0 = blockIdx.x * M_TILE;

    // Per-span table: {T[j-2..j+3], i1,i2a,i2b,i3a,i3b,i3c}, j = s+3
    float* tab = (float*)(sm + SMEM_TAB);
    if (t < 9) {
        const int j = t + 3;
        float* e = tab + t * 12;
        e[0] = knotv(j - 2); e[1] = knotv(j - 1); e[2] = knotv(j);
        e[3] = knotv(j + 1); e[4] = knotv(j + 2); e[5] = knotv(j + 3);
        e[6]  = 1.0f / (e[3] - e[2]);
        e[7]  = 1.0f / (e[3] - e[1]);
        e[8]  = 1.0f / (e[4] - e[2]);
        e[9]  = 1.0f / (e[3] - e[0]);
        e[10] = 1.0f / (e[4] - e[1]);
        e[11] = 1.0f / (e[5] - e[2]);
    }
    __syncthreads();

    // ---------------- Phase 1: build A tile in SMEM (fp16) ----------------
    // 64 rows x 16 i-quads = 1024 tasks, 8 per thread.
    #pragma unroll
    for (int s = 0; s < 8; s++) {
        const int p = s * THREADS + t;
        const int r = p >> 4;
        const int iq = p & 15;
        const int row = min(row0 + r, nrows - 1);

        const float4 xv = __ldg((const float4*)(x + (size_t)row * DIMS + iq * 4));
        const uint32_t wbase = sb + (uint32_t)r * A_PITCH_B + (uint32_t)iq * 96u;

        uint64_t keep0 = 0, keep1 = 0, keep2 = 0;
        #pragma unroll
        for (int u = 0; u < 4; u++) {
            float xc = (u == 0) ? xv.x : (u == 1) ? xv.y : (u == 2) ? xv.z : xv.w;
            xc = fminf(fmaxf(xc, 0.0f), 1.0f);

            const int s9 = min(8, (int)(xc * 9.0f));
            const float4* tb = (const float4*)(tab + s9 * 12);
            const float4 t0 = tb[0];
            const float4 t1 = tb[1];
            const float4 t2 = tb[2];

            const float l1 = xc - t0.z, r1 = t0.w - xc;
            const float l2 = xc - t0.y, r2 = t1.x - xc;
            const float l3 = xc - t0.x, r3 = t1.y - xc;

            float N0, N1, N2, N3, tmp, sv;
            tmp = t1.z;
            N0 = r1 * tmp; N1 = l1 * tmp;
            tmp = N0 * t1.w;
            N0 = r1 * tmp; sv = l2 * tmp;
            tmp = N1 * t2.x;
            N1 = fmaf(r2, tmp, sv); N2 = l1 * tmp;
            tmp = N0 * t2.y;
            N0 = r1 * tmp; sv = l3 * tmp;
            tmp = N1 * t2.z;
            N1 = fmaf(r2, tmp, sv); sv = l2 * tmp;
            tmp = N2 * t2.w;
            N2 = fmaf(r3, tmp, sv); N3 = l1 * tmp;

            const uint64_t w64 = (uint64_t)packh2(N0, N1)
                               | ((uint64_t)packh2(N2, N3) << 32);
            const int sl = s9 >> 2;
            const int rs = (s9 & 3) * 16;
            const uint64_t lo = w64 << rs;
            const uint64_t hi = rs ? (w64 >> (64 - rs)) : 0ULL;

            const uint64_t a0 = (sl == 0) ? lo : 0ULL;
            const uint64_t a1 = (sl == 1) ? lo : ((sl == 0) ? hi : 0ULL);
            const uint64_t a2 = (sl == 2) ? lo : ((sl == 1) ? hi : 0ULL);

            if ((u & 1) == 0) {
                keep0 = a0; keep1 = a1; keep2 = a2;
            } else {
                const uint32_t base = wbase + (uint32_t)(u >> 1) * 48u;
                asm volatile("st.shared.v2.u64 [%0], {%1, %2};"
                             :: "r"(base),      "l"(keep0), "l"(keep1) : "memory");
                asm volatile("st.shared.v2.u64 [%0], {%1, %2};"
                             :: "r"(base + 16), "l"(keep2), "l"(a0) : "memory");
                asm volatile("st.shared.v2.u64 [%0], {%1, %2};"
                             :: "r"(base + 32), "l"(a1), "l"(a2) : "memory");
            }
        }
    }
    __syncthreads();

    // ---------------- Phase 2: mma.sync mainloop (pipelined) ----------------
    const int mbase = (wid >> 1) * 32;      // 0, 32
    const int nb    = wid & 1;              // N group 0/1 -> nbase = nb*32

    const int lrow = (lid & 7) + ((lid >> 3) & 1) * 8;
    const int lcol = (lid >> 4) * 16;
    const uint32_t aAddr0 = sb + (uint32_t)(mbase + lrow) * A_PITCH_B + lcol;
    const uint32_t aAddr1 = aAddr0 + 16u * A_PITCH_B;

    const uint4* __restrict__ Bf = g_Bf2 + (size_t)(nb * 64 + lid * 2);

    float acc[2][4][4];
    #pragma unroll
    for (int mt = 0; mt < 2; mt++)
        #pragma unroll
        for (int nt = 0; nt < 4; nt++)
            #pragma unroll
            for (int q = 0; q < 4; q++) acc[mt][nt][q] = 0.0f;

    uint32_t a[2][8];
    uint4 bb[2][2];

    // prologue: stage ks=0
    ldsm_x4(a[0][0], a[0][1], a[0][2], a[0][3], aAddr0);
    ldsm_x4(a[0][4], a[0][5], a[0][6], a[0][7], aAddr1);
    bb[0][0] = __ldg(Bf + 0);
    bb[0][1] = __ldg(Bf + 1);

    #pragma unroll 4
    for (int ks = 0; ks < KSTEPS; ks++) {
        const int cur = ks & 1;
        const int nxt = cur ^ 1;
        if (ks + 1 < KSTEPS) {
            ldsm_x4(a[nxt][0], a[nxt][1], a[nxt][2], a[nxt][3],
                    aAddr0 + (ks + 1) * 32);
            ldsm_x4(a[nxt][4], a[nxt][5], a[nxt][6], a[nxt][7],
                    aAddr1 + (ks + 1) * 32);
            bb[nxt][0] = __ldg(Bf + (ks + 1) * 128 + 0);
            bb[nxt][1] = __ldg(Bf + (ks + 1) * 128 + 1);
        }
        const uint32_t b0[4] = { bb[cur][0].x, bb[cur][0].z, bb[cur][1].x, bb[cur][1].z };
        const uint32_t b1[4] = { bb[cur][0].y, bb[cur][0].w, bb[cur][1].y, bb[cur][1].w };
        #pragma unroll
        for (int mt = 0; mt < 2; mt++)
            #pragma unroll
            for (int nt = 0; nt < 4; nt++)
                mma16816(acc[mt][nt][0], acc[mt][nt][1], acc[mt][nt][2], acc[mt][nt][3],
                         a[cur][mt * 4 + 0], a[cur][mt * 4 + 1],
                         a[cur][mt * 4 + 2], a[cur][mt * 4 + 3],
                         b0[nt], b1[nt]);
    }

    // ---------------- Epilogue: direct float2 stores ----------------
    const int rquad = lid >> 2;
    const int npair = (lid & 3) * 2;
    #pragma unroll
    for (int mt = 0; mt < 2; mt++) {
        #pragma unroll
        for (int nt = 0; nt < 4; nt++) {
            const int col = nb * 32 + nt * 8 + npair;
            const int rA = row0 + mbase + mt * 16 + rquad;
            const int rB = rA + 8;
            if (rA < nrows)
                *(float2*)(out + (size_t)rA * DIMS + col) =
                    make_float2(acc[mt][nt][0], acc[mt][nt][1]);
            if (rB < nrows)
                *(float2*)(out + (size_t)rB * DIMS + col) =
                    make_float2(acc[mt][nt][2], acc[mt][nt][3]);
        }
    }
}

extern "C" void kernel_launch(void* const* d_in, const int* in_sizes, int n_in,
                              void* d_out, int out_size)
{
    const float* x  = (const float*)d_in[0];   // (65536, 64)
    const float* cp = (const float*)d_in[1];   // (64, 12, 64) == B[768][64]
    float* out = (float*)d_out;

    const int nrows = in_sizes[0] / DIMS;

    bspline_prep_kernel<<<(KSTEPS * 2 * 32 * 2 + 255) / 256, 256>>>(cp);

    cudaFuncSetAttribute(bspline_hmma_kernel,
                         cudaFuncAttributeMaxDynamicSharedMemorySize, SMEM_TOTAL);
    const int grid = (nrows + M_TILE - 1) / M_TILE;
    bspline_hmma_kernel<<<grid, THREADS, SMEM_TOTAL>>>(x, out, nrows);
}